// round 1
// baseline (speedup 1.0000x reference)
#include <cuda_runtime.h>
#include <math.h>

// Problem dims
#define N_TOK 2048
#define CDIM  1024
#define RH    256          // router hidden = C/4
#define NE    8            // experts
#define IDIM  4096         // intermediate
#define SEG   2048         // fixed rows per expert segment (max possible)
#define R_EXP (NE*SEG)     // 16384 expert rows
#define R_TOT (R_EXP + N_TOK)   // + shared-expert segment = 18432
#define MT_TOT (R_TOT/128)      // 144 row tiles (128 expert + 16 shared)

// Scratch (device globals; no allocations allowed)
__device__ float g_y1[N_TOK * RH];                 // router hidden, 2 MB
__device__ float g_h[(size_t)R_TOT * IDIM];        // silu(x@W1+b1) scratch, ~302 MB
__device__ int   g_cnt[NE];                        // tokens routed per expert
__device__ int   g_ptok[R_EXP];                    // token index per expert row
__device__ float g_pw[R_EXP];                      // combine weight per expert row

// ---------------------------------------------------------------------------
// 0) zero output + counters
// ---------------------------------------------------------------------------
__global__ void init_kernel(float* __restrict__ out) {
    int i = blockIdx.x * blockDim.x + threadIdx.x;
    if (i < N_TOK * CDIM) out[i] = 0.0f;
    if (i < NE) g_cnt[i] = 0;
}

// ---------------------------------------------------------------------------
// 1) router GEMM1: y1 = relu(x @ rw1 + rb1)   [2048 x 256], K=1024
//    128x128 tile, 256 threads, 8x8 microtile. grid (2, 16)
// ---------------------------------------------------------------------------
__global__ void __launch_bounds__(256, 2)
router_gemm(const float* __restrict__ x,
            const float* __restrict__ rw1,
            const float* __restrict__ rb1) {
    __shared__ float As[8][128];
    __shared__ float Bs[8][128];

    const int tid = threadIdx.x;
    const int m0 = blockIdx.y * 128;
    const int n0 = blockIdx.x * 128;

    const int ar = tid >> 1;            // row within tile (0..127)
    const int kh = (tid & 1) * 4;       // k-offset (0 or 4)
    const int kb = tid >> 5;            // 0..7
    const int bn = (tid & 31) * 4;      // 0..124

    const float* arow = x + (size_t)(m0 + ar) * CDIM;
    const float* bptr = rw1 + (size_t)kb * RH + n0 + bn;

    const int tm = (tid >> 4) * 8;
    const int tn = (tid & 15) * 8;

    float acc[8][8];
#pragma unroll
    for (int i = 0; i < 8; i++)
#pragma unroll
        for (int j = 0; j < 8; j++) acc[i][j] = 0.0f;

    for (int k0 = 0; k0 < CDIM; k0 += 8) {
        float4 av = *(const float4*)(arow + k0 + kh);
        As[kh + 0][ar] = av.x; As[kh + 1][ar] = av.y;
        As[kh + 2][ar] = av.z; As[kh + 3][ar] = av.w;
        *(float4*)&Bs[kb][bn] = *(const float4*)(bptr + (size_t)k0 * RH);
        __syncthreads();
#pragma unroll
        for (int kk = 0; kk < 8; kk++) {
            float a[8], b[8];
#pragma unroll
            for (int i = 0; i < 8; i++) a[i] = As[kk][tm + i];
#pragma unroll
            for (int j = 0; j < 8; j++) b[j] = Bs[kk][tn + j];
#pragma unroll
            for (int i = 0; i < 8; i++)
#pragma unroll
                for (int j = 0; j < 8; j++) acc[i][j] += a[i] * b[j];
        }
        __syncthreads();
    }

    float bb[8];
#pragma unroll
    for (int j = 0; j < 8; j++) bb[j] = rb1[n0 + tn + j];
#pragma unroll
    for (int i = 0; i < 8; i++) {
        float* yrow = g_y1 + (size_t)(m0 + tm + i) * RH + n0 + tn;
#pragma unroll
        for (int j = 0; j < 8; j++) {
            float v = acc[i][j] + bb[j];
            yrow[j] = v > 0.0f ? v : 0.0f;
        }
    }
}

// ---------------------------------------------------------------------------
// 2) router logits + softmax + top2 + re-softmax + scatter into segments
//    one thread per token. grid 8, block 256.
// ---------------------------------------------------------------------------
__global__ void route_kernel(const float* __restrict__ rw2,
                             const float* __restrict__ rb2) {
    __shared__ float s_w[RH * NE];   // 8 KB
    __shared__ float s_b[NE];
    const int tid = threadIdx.x;
    for (int i = tid; i < RH * NE; i += 256) s_w[i] = rw2[i];
    if (tid < NE) s_b[tid] = rb2[tid];
    __syncthreads();

    const int n = blockIdx.x * 256 + tid;
    const float* y = g_y1 + (size_t)n * RH;

    float acc[NE];
#pragma unroll
    for (int e = 0; e < NE; e++) acc[e] = s_b[e];
    for (int c = 0; c < RH; c++) {
        float v = y[c];
#pragma unroll
        for (int e = 0; e < NE; e++) acc[e] += v * s_w[c * NE + e];
    }

    // softmax over 8
    float m = acc[0];
#pragma unroll
    for (int e = 1; e < NE; e++) m = fmaxf(m, acc[e]);
    float s = 0.0f;
    float g[NE];
#pragma unroll
    for (int e = 0; e < NE; e++) { g[e] = expf(acc[e] - m); s += g[e]; }
    float inv = 1.0f / s;
#pragma unroll
    for (int e = 0; e < NE; e++) g[e] *= inv;

    // top-2 (descending, first index wins ties — matches lax.top_k)
    int i1 = 0; float g1 = g[0];
#pragma unroll
    for (int e = 1; e < NE; e++) if (g[e] > g1) { g1 = g[e]; i1 = e; }
    int i2 = -1; float g2 = -1.0f;
#pragma unroll
    for (int e = 0; e < NE; e++)
        if (e != i1 && g[e] > g2) { g2 = g[e]; i2 = e; }

    // softmax([g1/2, g2/2])
    float t  = expf((g2 - g1) * 0.5f);
    float d  = 1.0f / (1.0f + t);
    float w1 = d;
    float w2 = t * d;

    int p1 = atomicAdd(&g_cnt[i1], 1);
    g_ptok[i1 * SEG + p1] = n; g_pw[i1 * SEG + p1] = w1;
    int p2 = atomicAdd(&g_cnt[i2], 1);
    g_ptok[i2 * SEG + p2] = n; g_pw[i2 * SEG + p2] = w2;
}

// ---------------------------------------------------------------------------
// 3) grouped GEMM1: h[r,:] = silu(x[tok[r],:] @ W1[e] + b1[e])
//    grid (IDIM/128 = 32, MT_TOT = 144). Inactive tiles early-exit.
// ---------------------------------------------------------------------------
__global__ void __launch_bounds__(256, 2)
gemm1_kernel(const float* __restrict__ x,
             const float* __restrict__ ew1,
             const float* __restrict__ eb1,
             const float* __restrict__ sw1,
             const float* __restrict__ sb1) {
    const int t  = blockIdx.y;          // row tile
    const int n0 = blockIdx.x * 128;    // i offset
    const int tid = threadIdx.x;

    __shared__ int s_tok[128];
    __shared__ float As[8][128];
    __shared__ float Bs[8][128];

    const float* W;
    const float* bias;
    if (t < 128) {
        int e = t >> 4;
        int cnt = g_cnt[e];
        int lr0 = (t & 15) * 128;
        if (lr0 >= cnt) return;        // whole tile inactive
        W = ew1 + (size_t)e * CDIM * IDIM;
        bias = eb1 + (size_t)e * IDIM;
        if (tid < 128) {
            int lr = lr0 + tid;
            s_tok[tid] = (lr < cnt) ? g_ptok[e * SEG + lr] : 0;
        }
    } else {
        W = sw1; bias = sb1;
        if (tid < 128) s_tok[tid] = (t - 128) * 128 + tid;
    }
    __syncthreads();

    const int ar = tid >> 1;
    const int kh = (tid & 1) * 4;
    const int kb = tid >> 5;
    const int bn = (tid & 31) * 4;

    const float* arow = x + (size_t)s_tok[ar] * CDIM;
    const float* bptr = W + (size_t)kb * IDIM + n0 + bn;

    const int tm = (tid >> 4) * 8;
    const int tn = (tid & 15) * 8;

    float acc[8][8];
#pragma unroll
    for (int i = 0; i < 8; i++)
#pragma unroll
        for (int j = 0; j < 8; j++) acc[i][j] = 0.0f;

    for (int k0 = 0; k0 < CDIM; k0 += 8) {
        float4 av = *(const float4*)(arow + k0 + kh);
        As[kh + 0][ar] = av.x; As[kh + 1][ar] = av.y;
        As[kh + 2][ar] = av.z; As[kh + 3][ar] = av.w;
        *(float4*)&Bs[kb][bn] = *(const float4*)(bptr + (size_t)k0 * IDIM);
        __syncthreads();
#pragma unroll
        for (int kk = 0; kk < 8; kk++) {
            float a[8], b[8];
#pragma unroll
            for (int i = 0; i < 8; i++) a[i] = As[kk][tm + i];
#pragma unroll
            for (int j = 0; j < 8; j++) b[j] = Bs[kk][tn + j];
#pragma unroll
            for (int i = 0; i < 8; i++)
#pragma unroll
                for (int j = 0; j < 8; j++) acc[i][j] += a[i] * b[j];
        }
        __syncthreads();
    }

    float bb[8];
#pragma unroll
    for (int j = 0; j < 8; j++) bb[j] = bias[n0 + tn + j];
#pragma unroll
    for (int i = 0; i < 8; i++) {
        float* hrow = g_h + (size_t)(t * 128 + tm + i) * IDIM + n0 + tn;
#pragma unroll
        for (int j = 0; j < 8; j++) {
            float v = acc[i][j] + bb[j];
            v = v / (1.0f + expf(-v));       // silu
            hrow[j] = v;
        }
    }
}

// ---------------------------------------------------------------------------
// 4) grouped GEMM2: out[tok[r],:] += w[r] * (h[r,:] @ W2[e] + b2[e])
//    grid (CDIM/128 = 8, MT_TOT = 144). K = IDIM = 4096.
// ---------------------------------------------------------------------------
__global__ void __launch_bounds__(256, 2)
gemm2_kernel(const float* __restrict__ ew2,
             const float* __restrict__ eb2,
             const float* __restrict__ sw2,
             const float* __restrict__ sb2,
             float* __restrict__ out) {
    const int t  = blockIdx.y;
    const int n0 = blockIdx.x * 128;
    const int tid = threadIdx.x;

    __shared__ int   s_tok[128];
    __shared__ float s_wt[128];
    __shared__ float As[8][128];
    __shared__ float Bs[8][128];

    const float* W;
    const float* bias;
    if (t < 128) {
        int e = t >> 4;
        int cnt = g_cnt[e];
        int lr0 = (t & 15) * 128;
        if (lr0 >= cnt) return;
        W = ew2 + (size_t)e * IDIM * CDIM;
        bias = eb2 + (size_t)e * CDIM;
        if (tid < 128) {
            int lr = lr0 + tid;
            if (lr < cnt) { s_tok[tid] = g_ptok[e * SEG + lr]; s_wt[tid] = g_pw[e * SEG + lr]; }
            else          { s_tok[tid] = 0;                    s_wt[tid] = 0.0f; }
        }
    } else {
        W = sw2; bias = sb2;
        if (tid < 128) { s_tok[tid] = (t - 128) * 128 + tid; s_wt[tid] = 1.0f; }
    }
    __syncthreads();

    const int ar = tid >> 1;
    const int kh = (tid & 1) * 4;
    const int kb = tid >> 5;
    const int bn = (tid & 31) * 4;

    const float* arow = g_h + (size_t)(t * 128 + ar) * IDIM;
    const float* bptr = W + (size_t)kb * CDIM + n0 + bn;

    const int tm = (tid >> 4) * 8;
    const int tn = (tid & 15) * 8;

    float acc[8][8];
#pragma unroll
    for (int i = 0; i < 8; i++)
#pragma unroll
        for (int j = 0; j < 8; j++) acc[i][j] = 0.0f;

    for (int k0 = 0; k0 < IDIM; k0 += 8) {
        float4 av = *(const float4*)(arow + k0 + kh);
        As[kh + 0][ar] = av.x; As[kh + 1][ar] = av.y;
        As[kh + 2][ar] = av.z; As[kh + 3][ar] = av.w;
        *(float4*)&Bs[kb][bn] = *(const float4*)(bptr + (size_t)k0 * CDIM);
        __syncthreads();
#pragma unroll
        for (int kk = 0; kk < 8; kk++) {
            float a[8], b[8];
#pragma unroll
            for (int i = 0; i < 8; i++) a[i] = As[kk][tm + i];
#pragma unroll
            for (int j = 0; j < 8; j++) b[j] = Bs[kk][tn + j];
#pragma unroll
            for (int i = 0; i < 8; i++)
#pragma unroll
                for (int j = 0; j < 8; j++) acc[i][j] += a[i] * b[j];
        }
        __syncthreads();
    }

    float bb[8];
#pragma unroll
    for (int j = 0; j < 8; j++) bb[j] = bias[n0 + tn + j];
#pragma unroll
    for (int i = 0; i < 8; i++) {
        int tok = s_tok[tm + i];
        float w = s_wt[tm + i];
        if (w != 0.0f) {
            float* orow = out + (size_t)tok * CDIM + n0 + tn;
#pragma unroll
            for (int j = 0; j < 8; j++)
                atomicAdd(&orow[j], w * (acc[i][j] + bb[j]));
        }
    }
}

// ---------------------------------------------------------------------------
extern "C" void kernel_launch(void* const* d_in, const int* in_sizes, int n_in,
                              void* d_out, int out_size) {
    const float* x   = (const float*)d_in[0];
    const float* rw1 = (const float*)d_in[1];
    const float* rb1 = (const float*)d_in[2];
    const float* rw2 = (const float*)d_in[3];
    const float* rb2 = (const float*)d_in[4];
    const float* ew1 = (const float*)d_in[5];
    const float* eb1 = (const float*)d_in[6];
    const float* ew2 = (const float*)d_in[7];
    const float* eb2 = (const float*)d_in[8];
    const float* sw1 = (const float*)d_in[9];
    const float* sb1 = (const float*)d_in[10];
    const float* sw2 = (const float*)d_in[11];
    const float* sb2 = (const float*)d_in[12];
    float* out = (float*)d_out;

    init_kernel<<<2048, 1024>>>(out);
    router_gemm<<<dim3(2, 16), 256>>>(x, rw1, rb1);
    route_kernel<<<8, 256>>>(rw2, rb2);
    gemm1_kernel<<<dim3(IDIM / 128, MT_TOT), 256>>>(x, ew1, eb1, sw1, sb1);
    gemm2_kernel<<<dim3(CDIM / 128, MT_TOT), 256>>>(ew2, eb2, sw2, sb2, out);
}